// round 5
// baseline (speedup 1.0000x reference)
#include <cuda_runtime.h>
#include <math_constants.h>

// Problem: B=128, L=4096, FILTER_SIZE=2, N_QUBITS=4, 10 classes.
// Analytic reduction: expval_k(b,ol) = K_k * g(b,ol),
//   K_k = cos(p_k1)cos(p_k2)cos(p_k3)   (CNOT ring conjugates Z0 -> Z1Z2Z3)
//   g   = cos(x[ol,1]) * cos(x[ol+1,0]) * cos(x[ol+1,1])
// logits[j] = bias[j] + sum_ol g(ol)*(K0*W[2ol,j]+K1*W[2ol+1,j]); softmax.
#define OL     4095
#define OLP    4096
#define NCLS   10
#define B_SZ   128
#define QPR    4                      // blocks (quarters) per row
#define NT     256
#define NWARP  (NT / 32)

// Folded, TRANSPOSED weights (transpose => lane-stride-16B coalesced loads).
__device__ __align__(16) float d_Wp[NCLS * OLP];
// Cross-block combine scratch (init'd by prep every call).
__device__ float d_logits[B_SZ * NCLS];
__device__ int   d_tick[B_SZ];

// ---------------------------------------------------------------------------
// Prep: fold+transpose W, init logits scratch with bias, zero tickets.
// 32 blocks x 256 threads; W slice staged in smem via coalesced float4 loads.
// ---------------------------------------------------------------------------
__global__ __launch_bounds__(256) void qcnn_prep(const float* __restrict__ params,
                                                 const float* __restrict__ W,
                                                 const float* __restrict__ bias)
{
    __shared__ float sw[2560];
    const int bid = blockIdx.x, tid = threadIdx.x;
    const int W_F4 = 20475;                     // float4 count of W (81900 floats)

    const float4* w4 = (const float4*)W;
    const int f4base = bid * 640;
#pragma unroll
    for (int k = 0; k < 3; ++k) {
        int li = tid + k * 256;
        if (li < 640) {
            int gi = f4base + li;
            float4 v = (gi < W_F4) ? w4[gi] : make_float4(0.f, 0.f, 0.f, 0.f);
            *(float4*)&sw[4 * li] = v;
        }
    }

    // init combine scratch (independent of smem stage)
    int g = bid * 256 + tid;
    if (g < B_SZ * NCLS) d_logits[g] = bias[g % NCLS];
    if (g < B_SZ)        d_tick[g] = 0;
    __syncthreads();

    if (tid < 128) {
        float K0 = __cosf(params[1]) * __cosf(params[2]) * __cosf(params[3]);
        float K1 = __cosf(params[5]) * __cosf(params[6]) * __cosf(params[7]);
        int ol = bid * 128 + tid;
        const float* r = &sw[20 * tid];          // rows 2ol, 2ol+1 (10 floats each)
#pragma unroll
        for (int j = 0; j < NCLS; ++j)
            d_Wp[j * OLP + ol] = fmaf(K1, r[10 + j], K0 * r[j]);
    }
}

// ---------------------------------------------------------------------------
// Main: 512 blocks (4 per row) x 256 threads; 4 windows per thread.
// Neighbor pair via shfl.down (lane 31 loads one float2). Partial logits are
// atomically combined in gmem; the LAST block of each row does the softmax.
// ---------------------------------------------------------------------------
__global__ __launch_bounds__(NT, 4) void qcnn_main(const float* __restrict__ x,
                                                   float* __restrict__ out)
{
    __shared__ float sred[NWARP][NCLS];

    const int row = blockIdx.x >> 2;
    const int q   = blockIdx.x & 3;
    const int tid = threadIdx.x;
    const int T   = q * NT + tid;                // thread-in-row, 0..1023

    const float* xr = x + (size_t)row * OLP * 2;
    const float4* row4 = (const float4*)xr;
    float4 v0 = row4[2 * T];
    float4 v1 = row4[2 * T + 1];

    // pair 4T+4 = (x[8T+8], x[8T+9]) via shuffle; lane 31 from gmem
    float nx = __shfl_down_sync(0xFFFFFFFFu, v0.x, 1);
    float ny = __shfl_down_sync(0xFFFFFFFFu, v0.y, 1);
    if ((tid & 31) == 31) {
        int off = (T == OLP - 1) ? 0 : 8 * T + 8;   // last window: value unused
        float2 nb = *(const float2*)(xr + off);
        nx = nb.x; ny = nb.y;
    }

    // s1[i]=cos(x1), h[i]=cos(x0)*s1[i];  g_k = s1[k]*h[k+1]
    float s1_0 = __cosf(v0.y);
    float s1_1 = __cosf(v0.w), h1 = __cosf(v0.z) * s1_1;
    float s1_2 = __cosf(v1.y), h2 = __cosf(v1.x) * s1_2;
    float s1_3 = __cosf(v1.w), h3 = __cosf(v1.z) * s1_3;
    float h4   = __cosf(nx)   * __cosf(ny);
    float g0 = s1_0 * h1;
    float g1 = s1_1 * h2;
    float g2 = s1_2 * h3;
    float g3 = (T == OLP - 1) ? 0.0f : s1_3 * h4;   // window 4095 is padding

    // dot with folded weights: 10 coalesced, L2-hot LDG.128
    const float4* Wp4 = (const float4*)d_Wp;
    float acc[NCLS];
#pragma unroll
    for (int j = 0; j < NCLS; ++j) {
        float4 w = Wp4[j * (OLP / 4) + T];
        float a;
        a = g0 * w.x;
        a = fmaf(g1, w.y, a);
        a = fmaf(g2, w.z, a);
        a = fmaf(g3, w.w, a);
        acc[j] = a;
    }

    // block reduce 256 -> 10
#pragma unroll
    for (int j = 0; j < NCLS; ++j) {
#pragma unroll
        for (int off = 16; off; off >>= 1)
            acc[j] += __shfl_xor_sync(0xFFFFFFFFu, acc[j], off);
    }
    const int warp = tid >> 5, lane = tid & 31;
    if (lane == 0) {
#pragma unroll
        for (int j = 0; j < NCLS; ++j) sred[warp][j] = acc[j];
    }
    __syncthreads();

    // warp 0: combine into gmem; last block of the row does softmax
    if (tid < 32) {
        if (tid < NCLS) {
            float part = 0.0f;
#pragma unroll
            for (int w = 0; w < NWARP; ++w) part += sred[w][tid];
            atomicAdd(&d_logits[row * NCLS + tid], part);
        }
        __threadfence();
        int last = 0;
        if (tid == 0) last = (atomicAdd(&d_tick[row], 1) == QPR - 1);
        last = __shfl_sync(0xFFFFFFFFu, last, 0);
        if (last) {
            float logit = -CUDART_INF_F;
            if (tid < NCLS)                      // atomic read = L2-coherent
                logit = atomicAdd(&d_logits[row * NCLS + tid], 0.0f);
            float mx = logit;
#pragma unroll
            for (int off = 16; off; off >>= 1)
                mx = fmaxf(mx, __shfl_xor_sync(0xFFFFFFFFu, mx, off));
            float e = (tid < NCLS) ? __expf(logit - mx) : 0.0f;
            float s = e;
#pragma unroll
            for (int off = 16; off; off >>= 1)
                s += __shfl_xor_sync(0xFFFFFFFFu, s, off);
            if (tid < NCLS) out[row * NCLS + tid] = e / s;
        }
    }
}

// Inputs (metadata order): inputs(128*4096*2 f32), params(8 f32),
//                          W(8190*10 f32), b(10 f32). Output: (128*10) f32.
extern "C" void kernel_launch(void* const* d_in, const int* in_sizes, int n_in,
                              void* d_out, int out_size)
{
    const float* inputs = (const float*)d_in[0];
    const float* params = (const float*)d_in[1];
    const float* W      = (const float*)d_in[2];
    const float* bias   = (const float*)d_in[3];
    float* out          = (float*)d_out;

    qcnn_prep<<<32, 256>>>(params, W, bias);
    qcnn_main<<<B_SZ * QPR, NT>>>(inputs, out);
}